// round 8
// baseline (speedup 1.0000x reference)
#include <cuda_runtime.h>
#include <cuda_bf16.h>
#include <cstdint>

// Problem constants
#define BATCH  2
#define T_SEQ  2048
#define WID    1024
#define HEADS  16
#define CH     64
#define W3     3072
#define MROWS  (BATCH * T_SEQ)   // 4096

// Scratch (allocation-free rule: use __device__ globals)
__device__ float g_qkv [BATCH * T_SEQ * W3];    // 48 MB
__device__ float g_attn[BATCH * T_SEQ * WID];   // 16 MB
__device__ float g_kmean[BATCH * HEADS * CH];
__device__ float g_pos [BATCH * T_SEQ];
__device__ float g_aw  [BATCH * T_SEQ];

// ---------------------------------------------------------------------------
// mma.sync helpers (plain PTX — legal in compute_103 PTX)
// ---------------------------------------------------------------------------
__device__ __forceinline__ void mma_bf16(float* c, const uint32_t* a, const uint32_t* b)
{
    asm volatile(
        "mma.sync.aligned.m16n8k16.row.col.f32.bf16.bf16.f32 "
        "{%0,%1,%2,%3}, {%4,%5,%6,%7}, {%8,%9}, {%0,%1,%2,%3};"
        : "+f"(c[0]), "+f"(c[1]), "+f"(c[2]), "+f"(c[3])
        : "r"(a[0]), "r"(a[1]), "r"(a[2]), "r"(a[3]),
          "r"(b[0]), "r"(b[1]));
}

// Split two fp32 into packed bf16x2 hi + lo words (low half = first value).
__device__ __forceinline__ void bsplit2(float x0, float x1,
                                        uint32_t& hi, uint32_t& lo)
{
    __nv_bfloat16 h0 = __float2bfloat16(x0);
    __nv_bfloat16 h1 = __float2bfloat16(x1);
    float f0 = __bfloat162float(h0), f1 = __bfloat162float(h1);
    __nv_bfloat16 l0 = __float2bfloat16(x0 - f0);
    __nv_bfloat16 l1 = __float2bfloat16(x1 - f1);
    hi = (uint32_t)__bfloat16_as_ushort(h0) |
         ((uint32_t)__bfloat16_as_ushort(h1) << 16);
    lo = (uint32_t)__bfloat16_as_ushort(l0) |
         ((uint32_t)__bfloat16_as_ushort(l1) << 16);
}

// u32-packed A-frag (m16k16 bf16). lane = gid*4+tig; kw = k-word offset (k/2).
__device__ __forceinline__ void frag_au(uint32_t* a, const uint32_t* S, int SA,
                                        int r, int kw, int gid, int tig)
{
    const uint32_t* p0 = S + (r + gid) * SA + kw + tig;
    const uint32_t* p1 = S + (r + gid + 8) * SA + kw + tig;
    a[0] = p0[0]; a[1] = p1[0]; a[2] = p0[4]; a[3] = p1[4];
}

// ---------------------------------------------------------------------------
// Tensor-core GEMM, bf16x3, m16n8k16 — now DOUBLE-BUFFERED, 1 sync/iter.
// C[M,N] = A[M,K] @ B[K,N] + bias[N].
// CTA tile 128x128, K-chunk 32, 256 threads = 8 warps (4 M x 2 N).
// Buffer layout (u32): AH 0, AL 2560, BH 5120, BL 7296; buffer size 9472.
// Smem 2 x 37888 = 75776 B.
// ---------------------------------------------------------------------------
static constexpr int BA_S = 20;    // A u32 row stride
static constexpr int BB_S = 136;   // B u32 kp-row stride
static constexpr int GB_AL = 2560;
static constexpr int GB_BH = 5120;
static constexpr int GB_BL = 7296;
static constexpr int G_BUF = 9472;            // u32 per buffer
static constexpr int G_TOT = 2 * G_BUF * 4;   // 75776 bytes

__global__ __launch_bounds__(256, 2) void gemm_bf16(
    const float* __restrict__ A, const float* __restrict__ B,
    const float* __restrict__ bias, float* __restrict__ C,
    int N, int K)
{
    extern __shared__ uint32_t smu[];

    const int tid = threadIdx.x;
    const int wid = tid >> 5;
    const int lane = tid & 31;
    const int gid = lane >> 2, tig = lane & 3;
    const int wm = (wid >> 1) * 32;
    const int wn = (wid & 1) * 64;
    const int row0 = blockIdx.y * 128;
    const int col0 = blockIdx.x * 128;

    // stagers
    const int ar  = tid >> 1;           // 0..127
    const int ak  = (tid & 1) * 16;     // float offset 0 or 16
    const int bkp = tid >> 4;           // 0..15 (k-pair row)
    const int bn0 = (tid & 15) * 8;     // 0..120

    const float* Ap  = A + (size_t)(row0 + ar) * K + ak;
    const float* Bp0 = B + col0 + bn0;

    float c[2][8][4];
    #pragma unroll
    for (int i = 0; i < 2; i++)
        #pragma unroll
        for (int j = 0; j < 8; j++)
            #pragma unroll
            for (int q = 0; q < 4; q++) c[i][j][q] = 0.f;

    const int nIter = K >> 5;

    // ---- prologue: stage chunk 0 into buffer 0 ----
    {
        uint32_t* AH = smu;
        uint32_t* AL = smu + GB_AL;
        uint32_t* BH = smu + GB_BH;
        uint32_t* BL = smu + GB_BL;
        #pragma unroll
        for (int i = 0; i < 4; i++) {
            float4 v = *(const float4*)(Ap + i * 4);
            uint32_t h0, l0, h1, l1;
            bsplit2(v.x, v.y, h0, l0);
            bsplit2(v.z, v.w, h1, l1);
            const int w = ar * BA_S + ak / 2 + i * 2;
            AH[w] = h0; AH[w + 1] = h1;
            AL[w] = l0; AL[w + 1] = l1;
        }
        const float* Bp = Bp0 + (size_t)(2 * bkp) * N;
        float4 x0 = *(const float4*)(Bp);
        float4 x1 = *(const float4*)(Bp + 4);
        float4 y0 = *(const float4*)(Bp + N);
        float4 y1 = *(const float4*)(Bp + N + 4);
        const float xa[8] = {x0.x, x0.y, x0.z, x0.w, x1.x, x1.y, x1.z, x1.w};
        const float ya[8] = {y0.x, y0.y, y0.z, y0.w, y1.x, y1.y, y1.z, y1.w};
        #pragma unroll
        for (int cI = 0; cI < 8; cI++) {
            uint32_t hi, lo;
            bsplit2(xa[cI], ya[cI], hi, lo);
            BH[bkp * BB_S + bn0 + cI] = hi;
            BL[bkp * BB_S + bn0 + cI] = lo;
        }
    }
    __syncthreads();

    for (int it = 0; it < nIter; it++) {
        uint32_t* buf  = smu + (it & 1) * G_BUF;
        uint32_t* nbuf = smu + ((it + 1) & 1) * G_BUF;
        const bool has_next = (it + 1 < nIter);

        // ---- prefetch next chunk (gmem -> regs), hidden behind MMAs ----
        float4 av[4];
        float4 bx0, bx1, by0, by1;
        if (has_next) {
            const int kc = (it + 1) * 32;
            #pragma unroll
            for (int i = 0; i < 4; i++)
                av[i] = *(const float4*)(Ap + kc + i * 4);
            const float* Bp = Bp0 + (size_t)(kc + 2 * bkp) * N;
            bx0 = *(const float4*)(Bp);
            bx1 = *(const float4*)(Bp + 4);
            by0 = *(const float4*)(Bp + N);
            by1 = *(const float4*)(Bp + N + 4);
        }

        // ---- MMA on current buffer: 2 x k16 steps, bf16x3 ----
        {
            uint32_t* AH = buf;
            uint32_t* AL = buf + GB_AL;
            uint32_t* BH = buf + GB_BH;
            uint32_t* BL = buf + GB_BL;
            #pragma unroll
            for (int ks = 0; ks < 2; ks++) {
                uint32_t ah[2][4], al_[2][4];
                frag_au(ah[0],  AH, BA_S, wm,      ks * 8, gid, tig);
                frag_au(ah[1],  AH, BA_S, wm + 16, ks * 8, gid, tig);
                frag_au(al_[0], AL, BA_S, wm,      ks * 8, gid, tig);
                frag_au(al_[1], AL, BA_S, wm + 16, ks * 8, gid, tig);
                #pragma unroll
                for (int j = 0; j < 8; j++) {
                    const int base = (ks * 8 + tig) * BB_S + wn + j * 8 + gid;
                    uint32_t bh[2], bl[2];
                    bh[0] = BH[base]; bh[1] = BH[base + 4 * BB_S];
                    bl[0] = BL[base]; bl[1] = BL[base + 4 * BB_S];
                    #pragma unroll
                    for (int i = 0; i < 2; i++) {
                        mma_bf16(c[i][j], ah[i],  bh);
                        mma_bf16(c[i][j], ah[i],  bl);
                        mma_bf16(c[i][j], al_[i], bh);
                    }
                }
            }
        }

        // ---- split + store prefetched chunk into next buffer ----
        if (has_next) {
            uint32_t* AH = nbuf;
            uint32_t* AL = nbuf + GB_AL;
            uint32_t* BH = nbuf + GB_BH;
            uint32_t* BL = nbuf + GB_BL;
            #pragma unroll
            for (int i = 0; i < 4; i++) {
                uint32_t h0, l0, h1, l1;
                bsplit2(av[i].x, av[i].y, h0, l0);
                bsplit2(av[i].z, av[i].w, h1, l1);
                const int w = ar * BA_S + ak / 2 + i * 2;
                AH[w] = h0; AH[w + 1] = h1;
                AL[w] = l0; AL[w + 1] = l1;
            }
            const float xa[8] = {bx0.x, bx0.y, bx0.z, bx0.w,
                                 bx1.x, bx1.y, bx1.z, bx1.w};
            const float ya[8] = {by0.x, by0.y, by0.z, by0.w,
                                 by1.x, by1.y, by1.z, by1.w};
            #pragma unroll
            for (int cI = 0; cI < 8; cI++) {
                uint32_t hi, lo;
                bsplit2(xa[cI], ya[cI], hi, lo);
                BH[bkp * BB_S + bn0 + cI] = hi;
                BL[bkp * BB_S + bn0 + cI] = lo;
            }
        }
        __syncthreads();
    }

    // ---- epilogue: c frags + bias -> gmem ----
    #pragma unroll
    for (int i = 0; i < 2; i++) {
        const int r0 = row0 + wm + i * 16 + gid;
        #pragma unroll
        for (int j = 0; j < 8; j++) {
            const int col = col0 + wn + j * 8 + 2 * tig;
            float2 bv = *(const float2*)&bias[col];
            float2 o0 = make_float2(c[i][j][0] + bv.x, c[i][j][1] + bv.y);
            float2 o1 = make_float2(c[i][j][2] + bv.x, c[i][j][3] + bv.y);
            *(float2*)&C[(size_t)r0 * N + col]       = o0;
            *(float2*)&C[(size_t)(r0 + 8) * N + col] = o1;
        }
    }
}

// ---------------------------------------------------------------------------
// k_mean / pos / aw — unchanged
// ---------------------------------------------------------------------------
__global__ __launch_bounds__(256) void kmean_kernel()
{
    const int bh = blockIdx.x;
    const int b = bh >> 4, h = bh & 15;
    const int c  = threadIdx.x & 63;
    const int tg = threadIdx.x >> 6;
    const float* base = g_qkv + (size_t)b * T_SEQ * W3 + h * 192 + CH + c;
    float s = 0.f;
    for (int t = tg; t < T_SEQ; t += 4) s += base[(size_t)t * W3];
    __shared__ float red[4][64];
    red[tg][c] = s;
    __syncthreads();
    if (tg == 0) {
        float tot = red[0][c] + red[1][c] + red[2][c] + red[3][c];
        g_kmean[bh * CH + c] = tot * (1.f / (float)T_SEQ);
    }
}

__global__ __launch_bounds__(256) void pos_kernel()
{
    const int bt = blockIdx.x;
    const int b  = bt >> 11;
    const float* qb = g_qkv + (size_t)bt * W3;
    const float* km = g_kmean + b * WID;
    float s = 0.f;
    for (int j = threadIdx.x; j < WID; j += 256) {
        const int h = j >> 6, c = j & 63;
        s += qb[h * 192 + c] * km[j];
    }
    #pragma unroll
    for (int msk = 16; msk; msk >>= 1) s += __shfl_xor_sync(0xffffffffu, s, msk);
    __shared__ float red[8];
    if ((threadIdx.x & 31) == 0) red[threadIdx.x >> 5] = s;
    __syncthreads();
    if (threadIdx.x == 0) {
        float t = 0.f;
        #pragma unroll
        for (int w = 0; w < 8; w++) t += red[w];
        g_pos[bt] = t * 0.125f;
    }
}

__global__ __launch_bounds__(256) void aw_kernel()
{
    const int b = blockIdx.x;
    const int tid = threadIdx.x;
    float vals[8];
    float mn = 1e30f, mx = -1e30f;
    #pragma unroll
    for (int k = 0; k < 8; k++) {
        float v = g_pos[b * T_SEQ + tid + 256 * k];
        vals[k] = v;
        mn = fminf(mn, v);
        mx = fmaxf(mx, v);
    }
    __shared__ float smn[256], smx[256];
    smn[tid] = mn; smx[tid] = mx;
    __syncthreads();
    for (int s = 128; s; s >>= 1) {
        if (tid < s) {
            smn[tid] = fminf(smn[tid], smn[tid + s]);
            smx[tid] = fmaxf(smx[tid], smx[tid + s]);
        }
        __syncthreads();
    }
    const float gmn = smn[0];
    const float inv = 1.f / (smx[0] - smn[0] + 1e-6f);
    #pragma unroll
    for (int k = 0; k < 8; k++)
        g_aw[b * T_SEQ + tid + 256 * k] = (vals[k] - gmn) * inv;
}

// ---------------------------------------------------------------------------
// Flash attention — bf16x3, m16n8k16. P now stays IN REGISTERS:
// the S C-fragment (keys packed pairwise) IS the PV A-fragment, so the
// P smem staging (32 STS + 64 LDS + syncwarp per warp-chunk) is deleted.
// Smem 73728 B. 256 threads / 8 warps, Q-tile 128, K-chunk 64.
// ---------------------------------------------------------------------------
static constexpr int FQS = 36;   // Q/K u32 row stride
static constexpr int FVS = 72;   // V u32 row stride
static constexpr int U_QH = 0;
static constexpr int U_QL = U_QH + 128 * FQS;   // 4608
static constexpr int U_KH = U_QL + 128 * FQS;   // 9216
static constexpr int U_KL = U_KH + 64 * FQS;    // 11520
static constexpr int U_VH = U_KL + 64 * FQS;    // 13824
static constexpr int U_VL = U_VH + 32 * FVS;    // 16128
static constexpr int FA_TOT = (U_VL + 32 * FVS) * 4;  // 73728 bytes

__global__ __launch_bounds__(256, 2) void flash_attn_tc()
{
    extern __shared__ uint32_t smu[];
    uint32_t* QH = smu + U_QH;
    uint32_t* QL = smu + U_QL;
    uint32_t* KH = smu + U_KH;
    uint32_t* KL = smu + U_KL;
    uint32_t* VH = smu + U_VH;
    uint32_t* VL = smu + U_VL;

    const int tid = threadIdx.x;
    const int wid = tid >> 5;
    const int lane = tid & 31;
    const int gid = lane >> 2, tig = lane & 3;
    const int bh  = blockIdx.y;
    const int b = bh >> 4, h = bh & 15;
    const int q0 = blockIdx.x * 128;
    const float* base = g_qkv + (size_t)b * T_SEQ * W3 + h * 192;

    // ---- Load Q tile (128 rows): prescale 1/8, bf16-split, pack pairs ----
    {
        const int r = tid >> 1, c0 = (tid & 1) * 32;
        const float* qrow = base + (size_t)(q0 + r) * W3 + c0;
        #pragma unroll
        for (int i = 0; i < 8; i++) {
            float4 v = *(const float4*)(qrow + i * 4);
            uint32_t h0, l0, h1, l1;
            bsplit2(v.x * 0.125f, v.y * 0.125f, h0, l0);
            bsplit2(v.z * 0.125f, v.w * 0.125f, h1, l1);
            const int w = r * FQS + c0 / 2 + i * 2;
            QH[w] = h0; QH[w + 1] = h1;
            QL[w] = l0; QL[w + 1] = l1;
        }
    }

    const int wq = wid * 16;   // warp's q-row offset within tile

    float m0 = -1e30f, m1 = -1e30f, l0v = 0.f, l1v = 0.f;
    float O[8][4];
    #pragma unroll
    for (int j = 0; j < 8; j++)
        #pragma unroll
        for (int q = 0; q < 4; q++) O[j][q] = 0.f;

    for (int t0 = 0; t0 < T_SEQ; t0 += 64) {
        __syncthreads();   // all warps done with previous K/V
        // ---- stage K: 64 keys x 64 ch, packed along ch ----
        {
            const int r = tid >> 2, c0 = (tid & 3) * 16;
            const float* krow = base + (size_t)(t0 + r) * W3 + CH + c0;
            #pragma unroll
            for (int i = 0; i < 4; i++) {
                float4 v = *(const float4*)(krow + i * 4);
                uint32_t h0, l0, h1, l1;
                bsplit2(v.x, v.y, h0, l0);
                bsplit2(v.z, v.w, h1, l1);
                const int w = r * FQS + c0 / 2 + i * 2;
                KH[w] = h0; KH[w + 1] = h1;
                KL[w] = l0; KL[w + 1] = l1;
            }
        }
        // ---- stage V: packed along keys: word = (V[2kp][c], V[2kp+1][c]) ----
        {
            const int kp = tid >> 3, c0 = (tid & 7) * 8;
            const float* v0 = base + (size_t)(t0 + 2 * kp) * W3 + 2 * CH + c0;
            const float* v1 = v0 + W3;
            float4 a0 = *(const float4*)(v0);
            float4 a1 = *(const float4*)(v0 + 4);
            float4 b0 = *(const float4*)(v1);
            float4 b1 = *(const float4*)(v1 + 4);
            const float va[8] = {a0.x, a0.y, a0.z, a0.w, a1.x, a1.y, a1.z, a1.w};
            const float vb[8] = {b0.x, b0.y, b0.z, b0.w, b1.x, b1.y, b1.z, b1.w};
            #pragma unroll
            for (int c = 0; c < 8; c++) {
                uint32_t hi, lo;
                bsplit2(va[c], vb[c], hi, lo);
                VH[kp * FVS + c0 + c] = hi;
                VL[kp * FVS + c0 + c] = lo;
            }
        }
        __syncthreads();

        // ---- S = Q . K^T  (16 q-rows x 64 keys per warp), bf16x3 ----
        float s[8][4];
        #pragma unroll
        for (int j = 0; j < 8; j++)
            #pragma unroll
            for (int q = 0; q < 4; q++) s[j][q] = 0.f;
        #pragma unroll
        for (int ks = 0; ks < 4; ks++) {          // 4 x k16 over 64 channels
            uint32_t ah[4], al[4];
            frag_au(ah, QH, FQS, wq, ks * 8, gid, tig);
            frag_au(al, QL, FQS, wq, ks * 8, gid, tig);
            #pragma unroll
            for (int j = 0; j < 8; j++) {
                const int krow = (j * 8 + gid) * FQS + ks * 8 + tig;
                uint32_t bh[2], bl[2];
                bh[0] = KH[krow]; bh[1] = KH[krow + 4];
                bl[0] = KL[krow]; bl[1] = KL[krow + 4];
                mma_bf16(s[j], ah, bh);
                mma_bf16(s[j], ah, bl);
                mma_bf16(s[j], al, bh);
            }
        }

        // ---- online softmax (rows gid and gid+8) ----
        float mx0 = -1e30f, mx1 = -1e30f;
        #pragma unroll
        for (int j = 0; j < 8; j++) {
            mx0 = fmaxf(mx0, fmaxf(s[j][0], s[j][1]));
            mx1 = fmaxf(mx1, fmaxf(s[j][2], s[j][3]));
        }
        #pragma unroll
        for (int msk = 1; msk < 4; msk <<= 1) {
            mx0 = fmaxf(mx0, __shfl_xor_sync(0xffffffffu, mx0, msk));
            mx1 = fmaxf(mx1, __shfl_xor_sync(0xffffffffu, mx1, msk));
        }
        const float mn0 = fmaxf(m0, mx0), mn1 = fmaxf(m1, mx1);
        const float al0 = __expf(m0 - mn0), al1 = __expf(m1 - mn1);
        m0 = mn0; m1 = mn1;
        float sum0 = 0.f, sum1 = 0.f;
        #pragma unroll
        for (int j = 0; j < 8; j++) {
            s[j][0] = __expf(s[j][0] - mn0); sum0 += s[j][0];
            s[j][1] = __expf(s[j][1] - mn0); sum0 += s[j][1];
            s[j][2] = __expf(s[j][2] - mn1); sum1 += s[j][2];
            s[j][3] = __expf(s[j][3] - mn1); sum1 += s[j][3];
        }
        #pragma unroll
        for (int msk = 1; msk < 4; msk <<= 1) {
            sum0 += __shfl_xor_sync(0xffffffffu, sum0, msk);
            sum1 += __shfl_xor_sync(0xffffffffu, sum1, msk);
        }
        l0v = l0v * al0 + sum0;
        l1v = l1v * al1 + sum1;
        #pragma unroll
        for (int j = 0; j < 8; j++) {
            O[j][0] *= al0; O[j][1] *= al0;
            O[j][2] *= al1; O[j][3] *= al1;
        }

        // ---- O += P . V : P built directly from the S C-fragment.
        // A-frag for step kt = {pack(s[2kt][0,1]), pack(s[2kt][2,3]),
        //                       pack(s[2kt+1][0,1]), pack(s[2kt+1][2,3])}.
        #pragma unroll
        for (int kt = 0; kt < 4; kt++) {
            uint32_t ph[4], pl[4];
            bsplit2(s[2 * kt][0],     s[2 * kt][1],     ph[0], pl[0]);
            bsplit2(s[2 * kt][2],     s[2 * kt][3],     ph[1], pl[1]);
            bsplit2(s[2 * kt + 1][0], s[2 * kt + 1][1], ph[2], pl[2]);
            bsplit2(s[2 * kt + 1][2], s[2 * kt + 1][3], ph[3], pl[3]);
            #pragma unroll
            for (int j = 0; j < 8; j++) {
                const int vrow = (kt * 8 + tig) * FVS + j * 8 + gid;
                uint32_t bh[2], bl[2];
                bh[0] = VH[vrow]; bh[1] = VH[vrow + 4 * FVS];
                bl[0] = VL[vrow]; bl[1] = VL[vrow + 4 * FVS];
                mma_bf16(O[j], ph, bh);
                mma_bf16(O[j], ph, bl);
                mma_bf16(O[j], pl, bh);
            }
        }
    }

    // ---- epilogue: normalize, apply adaptive weight, write g_attn ----
    const int t0r = q0 + wq + gid;
    const int t1r = t0r + 8;
    const float w0 = g_aw[b * T_SEQ + t0r] / l0v;
    const float w1 = g_aw[b * T_SEQ + t1r] / l1v;
    float* o0 = g_attn + (size_t)(b * T_SEQ + t0r) * WID + h * CH;
    float* o1 = g_attn + (size_t)(b * T_SEQ + t1r) * WID + h * CH;
    #pragma unroll
    for (int j = 0; j < 8; j++) {
        const int cc = j * 8 + 2 * tig;
        *(float2*)(o0 + cc) = make_float2(O[j][0] * w0, O[j][1] * w0);
        *(float2*)(o1 + cc) = make_float2(O[j][2] * w1, O[j][3] * w1);
    }
}

// ---------------------------------------------------------------------------
extern "C" void kernel_launch(void* const* d_in, const int* in_sizes, int n_in,
                              void* d_out, int out_size)
{
    const float* x     = (const float*)d_in[0];
    const float* Wqkv  = (const float*)d_in[1];
    const float* bqkv  = (const float*)d_in[2];
    const float* Wproj = (const float*)d_in[3];
    const float* bproj = (const float*)d_in[4];
    float* out = (float*)d_out;

    float *qkv, *attn;
    cudaGetSymbolAddress((void**)&qkv,  g_qkv);
    cudaGetSymbolAddress((void**)&attn, g_attn);

    static bool attr_set = false;
    if (!attr_set) {
        cudaFuncSetAttribute(gemm_bf16, cudaFuncAttributeMaxDynamicSharedMemorySize, G_TOT);
        cudaFuncSetAttribute(flash_attn_tc, cudaFuncAttributeMaxDynamicSharedMemorySize, FA_TOT);
        attr_set = true;
    }

    // 1) qkv = x @ W_qkv + b_qkv       (tensor, bf16x3, double-buffered)
    gemm_bf16<<<dim3(W3 / 128, MROWS / 128), 256, G_TOT>>>(x, Wqkv, bqkv, qkv, W3, WID);
    // 2) k_mean
    kmean_kernel<<<BATCH * HEADS, 256>>>();
    // 3) pos = (q . k_mean)/8
    pos_kernel<<<BATCH * T_SEQ, 256>>>();
    // 4) adaptive weight
    aw_kernel<<<BATCH, 256>>>();
    // 5) attention (tensor, bf16x3, P in registers; applies aw)
    flash_attn_tc<<<dim3(T_SEQ / 128, BATCH * HEADS), 256, FA_TOT>>>();
    // 6) out = attn @ W_proj + b_proj  (tensor, bf16x3, double-buffered)
    gemm_bf16<<<dim3(WID / 128, MROWS / 128), 256, G_TOT>>>(attn, Wproj, bproj, out, WID, WID);
}

// round 9
// speedup vs baseline: 1.0398x; 1.0398x over previous
#include <cuda_runtime.h>
#include <cuda_bf16.h>
#include <cstdint>

// Problem constants
#define BATCH  2
#define T_SEQ  2048
#define WID    1024
#define HEADS  16
#define CH     64
#define W3     3072
#define MROWS  (BATCH * T_SEQ)   // 4096

// Scratch (allocation-free rule: use __device__ globals)
__device__ float g_qkv [BATCH * T_SEQ * W3];    // 48 MB
__device__ float g_attn[BATCH * T_SEQ * WID];   // 16 MB
__device__ float g_kmean[BATCH * HEADS * CH];
__device__ float g_pos [BATCH * T_SEQ];
__device__ float g_aw  [BATCH * T_SEQ];

// ---------------------------------------------------------------------------
// mma.sync helpers (plain PTX — legal in compute_103 PTX)
// ---------------------------------------------------------------------------
__device__ __forceinline__ void mma_bf16(float* c, const uint32_t* a, const uint32_t* b)
{
    asm volatile(
        "mma.sync.aligned.m16n8k16.row.col.f32.bf16.bf16.f32 "
        "{%0,%1,%2,%3}, {%4,%5,%6,%7}, {%8,%9}, {%0,%1,%2,%3};"
        : "+f"(c[0]), "+f"(c[1]), "+f"(c[2]), "+f"(c[3])
        : "r"(a[0]), "r"(a[1]), "r"(a[2]), "r"(a[3]),
          "r"(b[0]), "r"(b[1]));
}

// Split two fp32 into packed bf16x2 hi + lo words (low half = first value).
__device__ __forceinline__ void bsplit2(float x0, float x1,
                                        uint32_t& hi, uint32_t& lo)
{
    __nv_bfloat16 h0 = __float2bfloat16(x0);
    __nv_bfloat16 h1 = __float2bfloat16(x1);
    float f0 = __bfloat162float(h0), f1 = __bfloat162float(h1);
    __nv_bfloat16 l0 = __float2bfloat16(x0 - f0);
    __nv_bfloat16 l1 = __float2bfloat16(x1 - f1);
    hi = (uint32_t)__bfloat16_as_ushort(h0) |
         ((uint32_t)__bfloat16_as_ushort(h1) << 16);
    lo = (uint32_t)__bfloat16_as_ushort(l0) |
         ((uint32_t)__bfloat16_as_ushort(l1) << 16);
}

// u32-packed A-frag (m16k16 bf16). lane = gid*4+tig; kw = k-word offset (k/2).
__device__ __forceinline__ void frag_au(uint32_t* a, const uint32_t* S, int SA,
                                        int r, int kw, int gid, int tig)
{
    const uint32_t* p0 = S + (r + gid) * SA + kw + tig;
    const uint32_t* p1 = S + (r + gid + 8) * SA + kw + tig;
    a[0] = p0[0]; a[1] = p1[0]; a[2] = p0[4]; a[3] = p1[4];
}

// ---------------------------------------------------------------------------
// Tensor-core GEMM, bf16x3 on m16n8k16 — R7 version VERBATIM (validated,
// single-buffer; the R8 double-buffer variant regressed and is reverted).
// C[M,N] = A[M,K] @ B[K,N] + bias[N].
// CTA tile 128x128, K-chunk 32, 256 threads = 8 warps (4 M x 2 N).
// A stride 20 u32, B stride 136 u32 (both conflict-free). Smem 37888 B.
// ---------------------------------------------------------------------------
static constexpr int BA_S = 20;    // A u32 row stride (16 words + pad)
static constexpr int BB_S = 136;   // B u32 kp-row stride (128 words + pad)
static constexpr int GB_AH = 0;
static constexpr int GB_AL = 128 * BA_S;             // 2560
static constexpr int GB_BH = 2 * 128 * BA_S;         // 5120
static constexpr int GB_BL = GB_BH + 16 * BB_S;      // 7296
static constexpr int G_TOT = (GB_BL + 16 * BB_S) * 4; // 37888 bytes

__global__ __launch_bounds__(256) void gemm_bf16(
    const float* __restrict__ A, const float* __restrict__ B,
    const float* __restrict__ bias, float* __restrict__ C,
    int N, int K)
{
    extern __shared__ uint32_t smu[];
    uint32_t* AH = smu + GB_AH;
    uint32_t* AL = smu + GB_AL;
    uint32_t* BH = smu + GB_BH;
    uint32_t* BL = smu + GB_BL;

    const int tid = threadIdx.x;
    const int wid = tid >> 5;
    const int lane = tid & 31;
    const int gid = lane >> 2, tig = lane & 3;
    const int wm = (wid >> 1) * 32;   // warp row offset in tile
    const int wn = (wid & 1) * 64;    // warp col offset in tile
    const int row0 = blockIdx.y * 128;
    const int col0 = blockIdx.x * 128;

    // stagers
    const int ar  = tid >> 1;           // 0..127
    const int ak  = (tid & 1) * 16;     // float offset 0 or 16
    const int bkp = tid >> 4;           // 0..15 (k-pair row)
    const int bn0 = (tid & 15) * 8;     // 0..120

    const float* Ap  = A + (size_t)(row0 + ar) * K + ak;
    const float* Bp0 = B + col0 + bn0;

    float c[2][8][4];
    #pragma unroll
    for (int i = 0; i < 2; i++)
        #pragma unroll
        for (int j = 0; j < 8; j++)
            #pragma unroll
            for (int q = 0; q < 4; q++) c[i][j][q] = 0.f;

    for (int kc = 0; kc < K; kc += 32) {
        __syncthreads();
        // ---- stage A (128 x 32 fp32 -> 128 x 16 u32 hi/lo) ----
        #pragma unroll
        for (int i = 0; i < 4; i++) {
            float4 v = *(const float4*)(Ap + kc + i * 4);
            uint32_t h0, l0, h1, l1;
            bsplit2(v.x, v.y, h0, l0);
            bsplit2(v.z, v.w, h1, l1);
            const int w = ar * BA_S + ak / 2 + i * 2;
            AH[w] = h0; AH[w + 1] = h1;
            AL[w] = l0; AL[w + 1] = l1;
        }
        // ---- stage B (32 x 128 fp32 -> 16 kp-rows x 128 u32 hi/lo) ----
        {
            const float* Bp = Bp0 + (size_t)(kc + 2 * bkp) * N;
            float4 x0 = *(const float4*)(Bp);
            float4 x1 = *(const float4*)(Bp + 4);
            float4 y0 = *(const float4*)(Bp + N);
            float4 y1 = *(const float4*)(Bp + N + 4);
            const float xa[8] = {x0.x, x0.y, x0.z, x0.w, x1.x, x1.y, x1.z, x1.w};
            const float ya[8] = {y0.x, y0.y, y0.z, y0.w, y1.x, y1.y, y1.z, y1.w};
            #pragma unroll
            for (int cI = 0; cI < 8; cI++) {
                uint32_t hi, lo;
                bsplit2(xa[cI], ya[cI], hi, lo);   // word = (B[k][n], B[k+1][n])
                BH[bkp * BB_S + bn0 + cI] = hi;
                BL[bkp * BB_S + bn0 + cI] = lo;
            }
        }
        __syncthreads();

        // ---- MMA: 2 x k16 steps, bf16x3 ----
        #pragma unroll
        for (int ks = 0; ks < 2; ks++) {
            uint32_t ah[2][4], al_[2][4];
            frag_au(ah[0],  AH, BA_S, wm,      ks * 8, gid, tig);
            frag_au(ah[1],  AH, BA_S, wm + 16, ks * 8, gid, tig);
            frag_au(al_[0], AL, BA_S, wm,      ks * 8, gid, tig);
            frag_au(al_[1], AL, BA_S, wm + 16, ks * 8, gid, tig);
            #pragma unroll
            for (int j = 0; j < 8; j++) {
                const int base = (ks * 8 + tig) * BB_S + wn + j * 8 + gid;
                uint32_t bh[2], bl[2];
                bh[0] = BH[base]; bh[1] = BH[base + 4 * BB_S];
                bl[0] = BL[base]; bl[1] = BL[base + 4 * BB_S];
                #pragma unroll
                for (int i = 0; i < 2; i++) {
                    mma_bf16(c[i][j], ah[i],  bh);
                    mma_bf16(c[i][j], ah[i],  bl);
                    mma_bf16(c[i][j], al_[i], bh);
                }
            }
        }
    }

    // ---- epilogue: c frags + bias -> gmem ----
    #pragma unroll
    for (int i = 0; i < 2; i++) {
        const int r0 = row0 + wm + i * 16 + gid;
        #pragma unroll
        for (int j = 0; j < 8; j++) {
            const int col = col0 + wn + j * 8 + 2 * tig;
            float2 bv = *(const float2*)&bias[col];
            float2 o0 = make_float2(c[i][j][0] + bv.x, c[i][j][1] + bv.y);
            float2 o1 = make_float2(c[i][j][2] + bv.x, c[i][j][3] + bv.y);
            *(float2*)&C[(size_t)r0 * N + col]       = o0;
            *(float2*)&C[(size_t)(r0 + 8) * N + col] = o1;
        }
    }
}

// ---------------------------------------------------------------------------
// k_mean / pos / aw — unchanged
// ---------------------------------------------------------------------------
__global__ __launch_bounds__(256) void kmean_kernel()
{
    const int bh = blockIdx.x;
    const int b = bh >> 4, h = bh & 15;
    const int c  = threadIdx.x & 63;
    const int tg = threadIdx.x >> 6;
    const float* base = g_qkv + (size_t)b * T_SEQ * W3 + h * 192 + CH + c;
    float s = 0.f;
    for (int t = tg; t < T_SEQ; t += 4) s += base[(size_t)t * W3];
    __shared__ float red[4][64];
    red[tg][c] = s;
    __syncthreads();
    if (tg == 0) {
        float tot = red[0][c] + red[1][c] + red[2][c] + red[3][c];
        g_kmean[bh * CH + c] = tot * (1.f / (float)T_SEQ);
    }
}

__global__ __launch_bounds__(256) void pos_kernel()
{
    const int bt = blockIdx.x;
    const int b  = bt >> 11;
    const float* qb = g_qkv + (size_t)bt * W3;
    const float* km = g_kmean + b * WID;
    float s = 0.f;
    for (int j = threadIdx.x; j < WID; j += 256) {
        const int h = j >> 6, c = j & 63;
        s += qb[h * 192 + c] * km[j];
    }
    #pragma unroll
    for (int msk = 16; msk; msk >>= 1) s += __shfl_xor_sync(0xffffffffu, s, msk);
    __shared__ float red[8];
    if ((threadIdx.x & 31) == 0) red[threadIdx.x >> 5] = s;
    __syncthreads();
    if (threadIdx.x == 0) {
        float t = 0.f;
        #pragma unroll
        for (int w = 0; w < 8; w++) t += red[w];
        g_pos[bt] = t * 0.125f;
    }
}

__global__ __launch_bounds__(256) void aw_kernel()
{
    const int b = blockIdx.x;
    const int tid = threadIdx.x;
    float vals[8];
    float mn = 1e30f, mx = -1e30f;
    #pragma unroll
    for (int k = 0; k < 8; k++) {
        float v = g_pos[b * T_SEQ + tid + 256 * k];
        vals[k] = v;
        mn = fminf(mn, v);
        mx = fmaxf(mx, v);
    }
    __shared__ float smn[256], smx[256];
    smn[tid] = mn; smx[tid] = mx;
    __syncthreads();
    for (int s = 128; s; s >>= 1) {
        if (tid < s) {
            smn[tid] = fminf(smn[tid], smn[tid + s]);
            smx[tid] = fmaxf(smx[tid], smx[tid + s]);
        }
        __syncthreads();
    }
    const float gmn = smn[0];
    const float inv = 1.f / (smx[0] - smn[0] + 1e-6f);
    #pragma unroll
    for (int k = 0; k < 8; k++)
        g_aw[b * T_SEQ + tid + 256 * k] = (vals[k] - gmn) * inv;
}

// ---------------------------------------------------------------------------
// Flash attention — bf16x3, m16n8k16, P IN REGISTERS (kept from R8):
// the S C-fragment (keys packed pairwise) IS the PV A-fragment.
// Smem 73728 B. 256 threads / 8 warps, Q-tile 128, K-chunk 64. 2 CTAs/SM.
// ---------------------------------------------------------------------------
static constexpr int FQS = 36;   // Q/K u32 row stride
static constexpr int FVS = 72;   // V u32 row stride
static constexpr int U_QH = 0;
static constexpr int U_QL = U_QH + 128 * FQS;   // 4608
static constexpr int U_KH = U_QL + 128 * FQS;   // 9216
static constexpr int U_KL = U_KH + 64 * FQS;    // 11520
static constexpr int U_VH = U_KL + 64 * FQS;    // 13824
static constexpr int U_VL = U_VH + 32 * FVS;    // 16128
static constexpr int FA_TOT = (U_VL + 32 * FVS) * 4;  // 73728 bytes

__global__ __launch_bounds__(256, 2) void flash_attn_tc()
{
    extern __shared__ uint32_t smu[];
    uint32_t* QH = smu + U_QH;
    uint32_t* QL = smu + U_QL;
    uint32_t* KH = smu + U_KH;
    uint32_t* KL = smu + U_KL;
    uint32_t* VH = smu + U_VH;
    uint32_t* VL = smu + U_VL;

    const int tid = threadIdx.x;
    const int wid = tid >> 5;
    const int lane = tid & 31;
    const int gid = lane >> 2, tig = lane & 3;
    const int bh  = blockIdx.y;
    const int b = bh >> 4, h = bh & 15;
    const int q0 = blockIdx.x * 128;
    const float* base = g_qkv + (size_t)b * T_SEQ * W3 + h * 192;

    // ---- Load Q tile (128 rows): prescale 1/8, bf16-split, pack pairs ----
    {
        const int r = tid >> 1, c0 = (tid & 1) * 32;
        const float* qrow = base + (size_t)(q0 + r) * W3 + c0;
        #pragma unroll
        for (int i = 0; i < 8; i++) {
            float4 v = *(const float4*)(qrow + i * 4);
            uint32_t h0, l0, h1, l1;
            bsplit2(v.x * 0.125f, v.y * 0.125f, h0, l0);
            bsplit2(v.z * 0.125f, v.w * 0.125f, h1, l1);
            const int w = r * FQS + c0 / 2 + i * 2;
            QH[w] = h0; QH[w + 1] = h1;
            QL[w] = l0; QL[w + 1] = l1;
        }
    }

    const int wq = wid * 16;   // warp's q-row offset within tile

    float m0 = -1e30f, m1 = -1e30f, l0v = 0.f, l1v = 0.f;
    float O[8][4];
    #pragma unroll
    for (int j = 0; j < 8; j++)
        #pragma unroll
        for (int q = 0; q < 4; q++) O[j][q] = 0.f;

    for (int t0 = 0; t0 < T_SEQ; t0 += 64) {
        __syncthreads();   // all warps done with previous K/V
        // ---- stage K: 64 keys x 64 ch, packed along ch ----
        {
            const int r = tid >> 2, c0 = (tid & 3) * 16;
            const float* krow = base + (size_t)(t0 + r) * W3 + CH + c0;
            #pragma unroll
            for (int i = 0; i < 4; i++) {
                float4 v = *(const float4*)(krow + i * 4);
                uint32_t h0, l0, h1, l1;
                bsplit2(v.x, v.y, h0, l0);
                bsplit2(v.z, v.w, h1, l1);
                const int w = r * FQS + c0 / 2 + i * 2;
                KH[w] = h0; KH[w + 1] = h1;
                KL[w] = l0; KL[w + 1] = l1;
            }
        }
        // ---- stage V: packed along keys: word = (V[2kp][c], V[2kp+1][c]) ----
        {
            const int kp = tid >> 3, c0 = (tid & 7) * 8;
            const float* v0 = base + (size_t)(t0 + 2 * kp) * W3 + 2 * CH + c0;
            const float* v1 = v0 + W3;
            float4 a0 = *(const float4*)(v0);
            float4 a1 = *(const float4*)(v0 + 4);
            float4 b0 = *(const float4*)(v1);
            float4 b1 = *(const float4*)(v1 + 4);
            const float va[8] = {a0.x, a0.y, a0.z, a0.w, a1.x, a1.y, a1.z, a1.w};
            const float vb[8] = {b0.x, b0.y, b0.z, b0.w, b1.x, b1.y, b1.z, b1.w};
            #pragma unroll
            for (int c = 0; c < 8; c++) {
                uint32_t hi, lo;
                bsplit2(va[c], vb[c], hi, lo);
                VH[kp * FVS + c0 + c] = hi;
                VL[kp * FVS + c0 + c] = lo;
            }
        }
        __syncthreads();

        // ---- S = Q . K^T  (16 q-rows x 64 keys per warp), bf16x3 ----
        float s[8][4];
        #pragma unroll
        for (int j = 0; j < 8; j++)
            #pragma unroll
            for (int q = 0; q < 4; q++) s[j][q] = 0.f;
        #pragma unroll
        for (int ks = 0; ks < 4; ks++) {          // 4 x k16 over 64 channels
            uint32_t ah[4], al[4];
            frag_au(ah, QH, FQS, wq, ks * 8, gid, tig);
            frag_au(al, QL, FQS, wq, ks * 8, gid, tig);
            #pragma unroll
            for (int j = 0; j < 8; j++) {
                const int krow = (j * 8 + gid) * FQS + ks * 8 + tig;
                uint32_t bh[2], bl[2];
                bh[0] = KH[krow]; bh[1] = KH[krow + 4];
                bl[0] = KL[krow]; bl[1] = KL[krow + 4];
                mma_bf16(s[j], ah, bh);
                mma_bf16(s[j], ah, bl);
                mma_bf16(s[j], al, bh);
            }
        }

        // ---- online softmax (rows gid and gid+8) ----
        float mx0 = -1e30f, mx1 = -1e30f;
        #pragma unroll
        for (int j = 0; j < 8; j++) {
            mx0 = fmaxf(mx0, fmaxf(s[j][0], s[j][1]));
            mx1 = fmaxf(mx1, fmaxf(s[j][2], s[j][3]));
        }
        #pragma unroll
        for (int msk = 1; msk < 4; msk <<= 1) {
            mx0 = fmaxf(mx0, __shfl_xor_sync(0xffffffffu, mx0, msk));
            mx1 = fmaxf(mx1, __shfl_xor_sync(0xffffffffu, mx1, msk));
        }
        const float mn0 = fmaxf(m0, mx0), mn1 = fmaxf(m1, mx1);
        const float al0 = __expf(m0 - mn0), al1 = __expf(m1 - mn1);
        m0 = mn0; m1 = mn1;
        float sum0 = 0.f, sum1 = 0.f;
        #pragma unroll
        for (int j = 0; j < 8; j++) {
            s[j][0] = __expf(s[j][0] - mn0); sum0 += s[j][0];
            s[j][1] = __expf(s[j][1] - mn0); sum0 += s[j][1];
            s[j][2] = __expf(s[j][2] - mn1); sum1 += s[j][2];
            s[j][3] = __expf(s[j][3] - mn1); sum1 += s[j][3];
        }
        #pragma unroll
        for (int msk = 1; msk < 4; msk <<= 1) {
            sum0 += __shfl_xor_sync(0xffffffffu, sum0, msk);
            sum1 += __shfl_xor_sync(0xffffffffu, sum1, msk);
        }
        l0v = l0v * al0 + sum0;
        l1v = l1v * al1 + sum1;
        #pragma unroll
        for (int j = 0; j < 8; j++) {
            O[j][0] *= al0; O[j][1] *= al0;
            O[j][2] *= al1; O[j][3] *= al1;
        }

        // ---- O += P . V : P built directly from the S C-fragment.
        #pragma unroll
        for (int kt = 0; kt < 4; kt++) {
            uint32_t ph[4], pl[4];
            bsplit2(s[2 * kt][0],     s[2 * kt][1],     ph[0], pl[0]);
            bsplit2(s[2 * kt][2],     s[2 * kt][3],     ph[1], pl[1]);
            bsplit2(s[2 * kt + 1][0], s[2 * kt + 1][1], ph[2], pl[2]);
            bsplit2(s[2 * kt + 1][2], s[2 * kt + 1][3], ph[3], pl[3]);
            #pragma unroll
            for (int j = 0; j < 8; j++) {
                const int vrow = (kt * 8 + tig) * FVS + j * 8 + gid;
                uint32_t bh[2], bl[2];
                bh[0] = VH[vrow]; bh[1] = VH[vrow + 4 * FVS];
                bl[0] = VL[vrow]; bl[1] = VL[vrow + 4 * FVS];
                mma_bf16(O[j], ph, bh);
                mma_bf16(O[j], ph, bl);
                mma_bf16(O[j], pl, bh);
            }
        }
    }

    // ---- epilogue: normalize, apply adaptive weight, write g_attn ----
    const int t0r = q0 + wq + gid;
    const int t1r = t0r + 8;
    const float w0 = g_aw[b * T_SEQ + t0r] / l0v;
    const float w1 = g_aw[b * T_SEQ + t1r] / l1v;
    float* o0 = g_attn + (size_t)(b * T_SEQ + t0r) * WID + h * CH;
    float* o1 = g_attn + (size_t)(b * T_SEQ + t1r) * WID + h * CH;
    #pragma unroll
    for (int j = 0; j < 8; j++) {
        const int cc = j * 8 + 2 * tig;
        *(float2*)(o0 + cc) = make_float2(O[j][0] * w0, O[j][1] * w0);
        *(float2*)(o1 + cc) = make_float2(O[j][2] * w1, O[j][3] * w1);
    }
}

// ---------------------------------------------------------------------------
extern "C" void kernel_launch(void* const* d_in, const int* in_sizes, int n_in,
                              void* d_out, int out_size)
{
    const float* x     = (const float*)d_in[0];
    const float* Wqkv  = (const float*)d_in[1];
    const float* bqkv  = (const float*)d_in[2];
    const float* Wproj = (const float*)d_in[3];
    const float* bproj = (const float*)d_in[4];
    float* out = (float*)d_out;

    float *qkv, *attn;
    cudaGetSymbolAddress((void**)&qkv,  g_qkv);
    cudaGetSymbolAddress((void**)&attn, g_attn);

    static bool attr_set = false;
    if (!attr_set) {
        cudaFuncSetAttribute(gemm_bf16, cudaFuncAttributeMaxDynamicSharedMemorySize, G_TOT);
        cudaFuncSetAttribute(flash_attn_tc, cudaFuncAttributeMaxDynamicSharedMemorySize, FA_TOT);
        attr_set = true;
    }

    // 1) qkv = x @ W_qkv + b_qkv       (tensor, bf16x3, R7 single-buffer)
    gemm_bf16<<<dim3(W3 / 128, MROWS / 128), 256, G_TOT>>>(x, Wqkv, bqkv, qkv, W3, WID);
    // 2) k_mean
    kmean_kernel<<<BATCH * HEADS, 256>>>();
    // 3) pos = (q . k_mean)/8
    pos_kernel<<<BATCH * T_SEQ, 256>>>();
    // 4) adaptive weight
    aw_kernel<<<BATCH, 256>>>();
    // 5) attention (tensor, bf16x3, P in registers; applies aw)
    flash_attn_tc<<<dim3(T_SEQ / 128, BATCH * HEADS), 256, FA_TOT>>>();
    // 6) out = attn @ W_proj + b_proj  (tensor, bf16x3, R7 single-buffer)
    gemm_bf16<<<dim3(WID / 128, MROWS / 128), 256, G_TOT>>>(attn, Wproj, bproj, out, WID, WID);
}